// round 1
// baseline (speedup 1.0000x reference)
#include <cuda_runtime.h>
#include <math.h>
#include <math_constants.h>

// Problem constants (fixed by setup_inputs)
#define D0   64      // input feature dim
#define HH   2       // heads
#define CC   64      // per-head channels
#define FF   128     // HH*CC
#define NMAX 80000   // NU + NI
#define EMAX 1280000

// ---------------- scratch (static __device__, no allocation) ----------------
__device__ float g_h   [(size_t)NMAX * FF];  // GEMM output (h0, then h1)
__device__ float g_x1  [(size_t)NMAX * FF];  // layer-0 output / layer-1 input
__device__ float g_out1[(size_t)NMAX * CC];  // layer-1 output (mean over heads)
__device__ float g_asrc[NMAX * HH];
__device__ float g_adst[NMAX * HH];
__device__ float g_emax[NMAX * HH];
__device__ float g_den [NMAX * HH];

// ---------------- helpers ----------------
__device__ __forceinline__ void atomicMaxF(float* addr, float v) {
    // sign-split trick: valid for mixed-sign IEEE floats, init = -inf
    if (v >= 0.0f) atomicMax((int*)addr, __float_as_int(v));
    else           atomicMin((unsigned int*)addr, __float_as_uint(v));
}

__device__ __forceinline__ float lrelu(float x) {
    return x >= 0.0f ? x : 0.2f * x;
}

// ---------------- GEMM: Y[n, FF] = X[n, K] @ W[K, FF] ----------------
// Row-split input: row r < split reads A, else B (for the Gu|Gi concat).
// blockDim = 128 (one thread per output column), RPB rows per block.
template<int K>
__global__ void gemm_rowpanel(const float* __restrict__ A,
                              const float* __restrict__ B,
                              int split,
                              const float* __restrict__ W,
                              float* __restrict__ Y,
                              int n) {
    const int RPB = 8;
    __shared__ float xs[RPB][K];
    int r0 = blockIdx.x * RPB;
    int t  = threadIdx.x;

    for (int idx = t; idx < RPB * K; idx += 128) {
        int r = idx / K, k = idx % K;
        int gr = r0 + r;
        float v = 0.0f;
        if (gr < n) {
            const float* src = (gr < split) ? (A + (size_t)gr * K)
                                            : (B + (size_t)(gr - split) * K);
            v = src[k];
        }
        xs[r][k] = v;
    }
    __syncthreads();

    float acc[RPB];
#pragma unroll
    for (int r = 0; r < RPB; ++r) acc[r] = 0.0f;

    for (int k = 0; k < K; ++k) {
        float w = W[k * FF + t];
#pragma unroll
        for (int r = 0; r < RPB; ++r) acc[r] += xs[r][k] * w;
    }

#pragma unroll
    for (int r = 0; r < RPB; ++r) {
        int gr = r0 + r;
        if (gr < n) Y[(size_t)gr * FF + t] = acc[r];
    }
}

// ---------------- per-node attention scalars ----------------
// warp per (node, head): a_src[n,h] = <h[n,h,:], att_src[h,:]>, same for dst.
__global__ void attn_scores(const float* __restrict__ h,
                            const float* __restrict__ att_src,
                            const float* __restrict__ att_dst,
                            int n) {
    int gw   = (blockIdx.x * blockDim.x + threadIdx.x) >> 5;
    int lane = threadIdx.x & 31;
    if (gw >= n * HH) return;
    int node = gw / HH, head = gw % HH;
    const float* hr = h + (size_t)node * FF + head * CC;

    float s = 0.0f, d = 0.0f;
#pragma unroll
    for (int c = lane; c < CC; c += 32) {
        float v = hr[c];
        s += v * att_src[head * CC + c];
        d += v * att_dst[head * CC + c];
    }
#pragma unroll
    for (int o = 16; o > 0; o >>= 1) {
        s += __shfl_down_sync(0xffffffffu, s, o);
        d += __shfl_down_sync(0xffffffffu, d, o);
    }
    if (lane == 0) { g_asrc[gw] = s; g_adst[gw] = d; }
}

// ---------------- init kernels ----------------
__global__ void init_softmax_state(int n) {
    int i = blockIdx.x * blockDim.x + threadIdx.x;
    if (i >= n * HH) return;
    g_emax[i] = -CUDART_INF_F;
    g_den[i]  = 0.0f;
}

__global__ void init_bias(float* __restrict__ out, const float* __restrict__ bias,
                          int n, int width) {
    int i = blockIdx.x * blockDim.x + threadIdx.x;
    if (i >= n * width) return;
    out[i] = bias[i % width];
}

// ---------------- edge passes ----------------
__global__ void edge_max(const int* __restrict__ src, const int* __restrict__ dst,
                         int E) {
    int e = blockIdx.x * blockDim.x + threadIdx.x;
    if (e >= E) return;
    int s = src[e], d = dst[e];
#pragma unroll
    for (int h = 0; h < HH; ++h) {
        float x = lrelu(g_asrc[s * HH + h] + g_adst[d * HH + h]);
        atomicMaxF(&g_emax[d * HH + h], x);
    }
}

__global__ void edge_den(const int* __restrict__ src, const int* __restrict__ dst,
                         int E) {
    int e = blockIdx.x * blockDim.x + threadIdx.x;
    if (e >= E) return;
    int s = src[e], d = dst[e];
#pragma unroll
    for (int h = 0; h < HH; ++h) {
        float x = lrelu(g_asrc[s * HH + h] + g_adst[d * HH + h]);
        atomicAdd(&g_den[d * HH + h], __expf(x - g_emax[d * HH + h]));
    }
}

// layer-0 aggregation (concat heads): out[d, 128] += alpha_h * h[s, 128]
// one warp per edge, lane i handles float4 i (heads split at lane 16)
__global__ void agg_concat(const int* __restrict__ src, const int* __restrict__ dst,
                           const float* __restrict__ h, float* __restrict__ out,
                           int E) {
    int warp = (blockIdx.x * blockDim.x + threadIdx.x) >> 5;
    int lane = threadIdx.x & 31;
    if (warp >= E) return;
    int s = src[warp], d = dst[warp];

    float al[HH];
#pragma unroll
    for (int hh = 0; hh < HH; ++hh) {
        float x = lrelu(g_asrc[s * HH + hh] + g_adst[d * HH + hh]);
        al[hh] = __expf(x - g_emax[d * HH + hh]) / (g_den[d * HH + hh] + 1e-16f);
    }

    float4 v = ((const float4*)(h + (size_t)s * FF))[lane];
    float  a = (lane < 16) ? al[0] : al[1];
    float* o = out + (size_t)d * FF + lane * 4;
    atomicAdd(o + 0, v.x * a);
    atomicAdd(o + 1, v.y * a);
    atomicAdd(o + 2, v.z * a);
    atomicAdd(o + 3, v.w * a);
}

// layer-1 aggregation (mean over heads): out[d, 64] += 0.5*(al0*h[s,0:64] + al1*h[s,64:128])
// one warp per edge, lane i handles float2 at columns {2i, 2i+1}
__global__ void agg_mean(const int* __restrict__ src, const int* __restrict__ dst,
                         const float* __restrict__ h, float* __restrict__ out,
                         int E) {
    int warp = (blockIdx.x * blockDim.x + threadIdx.x) >> 5;
    int lane = threadIdx.x & 31;
    if (warp >= E) return;
    int s = src[warp], d = dst[warp];

    float al[HH];
#pragma unroll
    for (int hh = 0; hh < HH; ++hh) {
        float x = lrelu(g_asrc[s * HH + hh] + g_adst[d * HH + hh]);
        al[hh] = __expf(x - g_emax[d * HH + hh]) / (g_den[d * HH + hh] + 1e-16f);
    }

    int c = lane * 2;
    float2 v0 = *(const float2*)(h + (size_t)s * FF + c);
    float2 v1 = *(const float2*)(h + (size_t)s * FF + CC + c);
    float* o = out + (size_t)d * CC + c;
    atomicAdd(o + 0, 0.5f * (al[0] * v0.x + al[1] * v1.x));
    atomicAdd(o + 1, 0.5f * (al[0] * v0.y + al[1] * v1.y));
}

// ---------------- final scorer: out[b] = <gu[user[b]], gi[item[b]]> ----------------
__global__ void score_pairs(const float* __restrict__ emb,
                            const int* __restrict__ uidx,
                            const int* __restrict__ iidx,
                            int nu, float* __restrict__ out, int B) {
    int warp = (blockIdx.x * blockDim.x + threadIdx.x) >> 5;
    int lane = threadIdx.x & 31;
    if (warp >= B) return;
    const float* gu = emb + (size_t)uidx[warp] * CC;
    const float* gi = emb + (size_t)(nu + iidx[warp]) * CC;
    float s = gu[lane] * gi[lane] + gu[lane + 32] * gi[lane + 32];
#pragma unroll
    for (int o = 16; o > 0; o >>= 1) s += __shfl_down_sync(0xffffffffu, s, o);
    if (lane == 0) out[warp] = s;
}

// ---------------- launch ----------------
extern "C" void kernel_launch(void* const* d_in, const int* in_sizes, int n_in,
                              void* d_out, int out_size) {
    const float* Gu  = (const float*)d_in[0];
    const float* Gi  = (const float*)d_in[1];
    const float* W0  = (const float*)d_in[2];
    const float* as0 = (const float*)d_in[3];
    const float* ad0 = (const float*)d_in[4];
    const float* b0  = (const float*)d_in[5];
    const float* W1  = (const float*)d_in[6];
    const float* as1 = (const float*)d_in[7];
    const float* ad1 = (const float*)d_in[8];
    const float* b1  = (const float*)d_in[9];
    const int*   ei  = (const int*)d_in[10];
    const int*   uix = (const int*)d_in[11];
    const int*   iix = (const int*)d_in[12];
    float* out = (float*)d_out;

    const int NU = in_sizes[0] / D0;
    const int NI = in_sizes[1] / D0;
    const int N  = NU + NI;
    const int E  = in_sizes[10] / 2;
    const int B  = in_sizes[11];
    const int* src = ei;
    const int* dst = ei + E;

    float *ph, *px1, *pout1;
    cudaGetSymbolAddress((void**)&ph,    g_h);
    cudaGetSymbolAddress((void**)&px1,   g_x1);
    cudaGetSymbolAddress((void**)&pout1, g_out1);

    const int TB = 256;
    int gemm_blocks = (N + 7) / 8;
    int warps_grid_E = (E * 32 + TB - 1) / TB;       // warp-per-edge grids
    int attn_grid    = (N * HH * 32 + TB - 1) / TB;  // warp-per-(node,head)
    int nh_grid      = (N * HH + TB - 1) / TB;
    int edge_grid    = (E + TB - 1) / TB;

    // ---------- layer 0 ----------
    gemm_rowpanel<D0><<<gemm_blocks, 128>>>(Gu, Gi, NU, W0, ph, N);
    attn_scores<<<attn_grid, TB>>>(ph, as0, ad0, N);
    init_softmax_state<<<nh_grid, TB>>>(N);
    init_bias<<<(N * FF + TB - 1) / TB, TB>>>(px1, b0, N, FF);
    edge_max<<<edge_grid, TB>>>(src, dst, E);
    edge_den<<<edge_grid, TB>>>(src, dst, E);
    agg_concat<<<warps_grid_E, TB>>>(src, dst, ph, px1, E);

    // ---------- layer 1 ----------
    gemm_rowpanel<FF><<<gemm_blocks, 128>>>(px1, px1, N, W1, ph, N);
    attn_scores<<<attn_grid, TB>>>(ph, as1, ad1, N);
    init_softmax_state<<<nh_grid, TB>>>(N);
    init_bias<<<(N * CC + TB - 1) / TB, TB>>>(pout1, b1, N, CC);
    edge_max<<<edge_grid, TB>>>(src, dst, E);
    edge_den<<<edge_grid, TB>>>(src, dst, E);
    agg_mean<<<warps_grid_E, TB>>>(src, dst, ph, pout1, E);

    // ---------- scorer ----------
    score_pairs<<<(B * 32 + TB - 1) / TB, TB>>>(pout1, uix, iix, NU, out, B);
}

// round 4
// speedup vs baseline: 2.4104x; 2.4104x over previous
#include <cuda_runtime.h>
#include <math.h>
#include <math_constants.h>

// Problem constants (fixed by setup_inputs)
#define D0   64
#define HH   2
#define CC   64
#define FF   128
#define NMAX 80000
#define EMAX 1280000
#define SCAN_BLK 1024

// ---------------- scratch ----------------
__device__ float g_h   [(size_t)NMAX * FF];
__device__ float g_x1  [(size_t)NMAX * FF];
__device__ float g_out1[(size_t)NMAX * CC];
__device__ float g_asrc[NMAX * HH];
__device__ float g_adst[NMAX * HH];
__device__ int   g_cnt   [NMAX];
__device__ int   g_start [NMAX];
__device__ int   g_cursor[NMAX];
__device__ int   g_part  [256];
__device__ int   g_csrsrc[EMAX];

__device__ __forceinline__ float lrelu(float x) {
    return x >= 0.0f ? x : 0.2f * x;
}

// ---------------- GEMM: Y[n, FF] = X[n, K] @ W[K, FF] ----------------
template<int K>
__global__ void gemm_rowpanel(const float* __restrict__ A,
                              const float* __restrict__ B,
                              int split,
                              const float* __restrict__ W,
                              float* __restrict__ Y,
                              int n) {
    const int RPB = 16;
    __shared__ float xs[RPB][K];
    int r0 = blockIdx.x * RPB;
    int t  = threadIdx.x;          // 0..255
    int col  = t & 127;
    int half = t >> 7;

    for (int idx = t; idx < RPB * K; idx += 256) {
        int r = idx / K, k = idx % K;
        int gr = r0 + r;
        float v = 0.0f;
        if (gr < n) {
            const float* src = (gr < split) ? (A + (size_t)gr * K)
                                            : (B + (size_t)(gr - split) * K);
            v = src[k];
        }
        xs[r][k] = v;
    }
    __syncthreads();

    float acc[8];
#pragma unroll
    for (int r = 0; r < 8; ++r) acc[r] = 0.0f;
    int rbase = half * 8;

    for (int k = 0; k < K; ++k) {
        float w = W[k * FF + col];
#pragma unroll
        for (int r = 0; r < 8; ++r) acc[r] += xs[rbase + r][k] * w;
    }

#pragma unroll
    for (int r = 0; r < 8; ++r) {
        int gr = r0 + rbase + r;
        if (gr < n) Y[(size_t)gr * FF + col] = acc[r];
    }
}

// ---------------- per-node attention scalars ----------------
__global__ void attn_scores(const float* __restrict__ h,
                            const float* __restrict__ att_src,
                            const float* __restrict__ att_dst,
                            int n) {
    int gw   = (blockIdx.x * blockDim.x + threadIdx.x) >> 5;
    int lane = threadIdx.x & 31;
    if (gw >= n * HH) return;
    int node = gw / HH, head = gw % HH;
    const float* hr = h + (size_t)node * FF + head * CC;

    float s = 0.0f, d = 0.0f;
#pragma unroll
    for (int c = lane; c < CC; c += 32) {
        float v = hr[c];
        s += v * att_src[head * CC + c];
        d += v * att_dst[head * CC + c];
    }
#pragma unroll
    for (int o = 16; o > 0; o >>= 1) {
        s += __shfl_down_sync(0xffffffffu, s, o);
        d += __shfl_down_sync(0xffffffffu, d, o);
    }
    if (lane == 0) { g_asrc[gw] = s; g_adst[gw] = d; }
}

// ---------------- CSR build ----------------
__global__ void zero_cnt(int n) {
    int i = blockIdx.x * blockDim.x + threadIdx.x;
    if (i < n) g_cnt[i] = 0;
}

__global__ void hist_dst(const int* __restrict__ dst, int E) {
    int e = blockIdx.x * blockDim.x + threadIdx.x;
    if (e < E) atomicAdd(&g_cnt[dst[e]], 1);
}

__global__ void scan1(int n) {
    __shared__ int sm[SCAN_BLK];
    int i = blockIdx.x * SCAN_BLK + threadIdx.x;
    int v = (i < n) ? g_cnt[i] : 0;
    sm[threadIdx.x] = v;
    __syncthreads();
    for (int off = 1; off < SCAN_BLK; off <<= 1) {
        int t = (threadIdx.x >= off) ? sm[threadIdx.x - off] : 0;
        __syncthreads();
        sm[threadIdx.x] += t;
        __syncthreads();
    }
    if (i < n) g_start[i] = sm[threadIdx.x] - v;   // exclusive
    if (threadIdx.x == SCAN_BLK - 1) g_part[blockIdx.x] = sm[SCAN_BLK - 1];
}

__global__ void scan2(int nblocks) {
    __shared__ int sm[256];
    int t = threadIdx.x;
    int v = (t < nblocks) ? g_part[t] : 0;
    sm[t] = v;
    __syncthreads();
    for (int off = 1; off < 256; off <<= 1) {
        int u = (t >= off) ? sm[t - off] : 0;
        __syncthreads();
        sm[t] += u;
        __syncthreads();
    }
    if (t < nblocks) g_part[t] = sm[t] - v;        // exclusive
}

__global__ void scan3(int n) {
    int i = blockIdx.x * SCAN_BLK + threadIdx.x;
    if (i >= n) return;
    int s = g_start[i] + g_part[blockIdx.x];
    g_start[i]  = s;
    g_cursor[i] = s;
}

__global__ void scatter_edges(const int* __restrict__ src,
                              const int* __restrict__ dst, int E) {
    int e = blockIdx.x * blockDim.x + threadIdx.x;
    if (e >= E) return;
    int pos = atomicAdd(&g_cursor[dst[e]], 1);
    g_csrsrc[pos] = src[e];
}

// ---------------- layer-0 aggregation (concat heads), CSR gather ----------------
// warp per dst node; lane l handles float4 cols [4l,4l+4); heads split at lane 16
__global__ void agg_concat_csr(const float* __restrict__ h,
                               const float* __restrict__ bias,
                               float* __restrict__ out, int n) {
    int d    = (blockIdx.x * blockDim.x + threadIdx.x) >> 5;
    int lane = threadIdx.x & 31;
    if (d >= n) return;
    int hsel = lane >> 4;

    float2 adp = ((const float2*)g_adst)[d];
    int start = g_start[d];
    int deg   = g_cnt[d];

    float4 acc = make_float4(0.f, 0.f, 0.f, 0.f);
    float  den = 0.f;

    // prefetch first chunk's indices
    int sj_next = 0;
    if (lane < deg) sj_next = g_csrsrc[start + lane];

    for (int base = 0; base < deg; base += 32) {
        int m = min(32, deg - base);
        int sj = sj_next;
        // prefetch next chunk's indices before consuming this one
        int nb = base + 32;
        if (nb + lane < deg) sj_next = g_csrsrc[start + nb + lane];

        float w0 = 0.f, w1 = 0.f;
        if (lane < m) {
            float2 as = ((const float2*)g_asrc)[sj];
            w0 = __expf(lrelu(as.x + adp.x));
            w1 = __expf(lrelu(as.y + adp.y));
        }
        for (int k = 0; k < m; ++k) {
            int   s  = __shfl_sync(0xffffffffu, sj, k);
            float wa = __shfl_sync(0xffffffffu, w0, k);
            float wb = __shfl_sync(0xffffffffu, w1, k);
            float w  = (hsel == 0) ? wa : wb;
            float4 v = ((const float4*)(h + (size_t)s * FF))[lane];
            acc.x += w * v.x; acc.y += w * v.y;
            acc.z += w * v.z; acc.w += w * v.w;
            den += w;
        }
    }
    float inv = 1.0f / (den + 1e-16f);
    float4 b  = ((const float4*)bias)[lane];
    float4 o  = make_float4(acc.x * inv + b.x, acc.y * inv + b.y,
                            acc.z * inv + b.z, acc.w * inv + b.w);
    ((float4*)(out + (size_t)d * FF))[lane] = o;
}

// ---------------- layer-1 aggregation (mean over heads), CSR gather ----------------
// warp per dst node; lane l handles cols {2l, 2l+1} of both heads
__global__ void agg_mean_csr(const float* __restrict__ h,
                             const float* __restrict__ bias,
                             float* __restrict__ out, int n) {
    int d    = (blockIdx.x * blockDim.x + threadIdx.x) >> 5;
    int lane = threadIdx.x & 31;
    if (d >= n) return;

    float2 adp = ((const float2*)g_adst)[d];
    int start = g_start[d];
    int deg   = g_cnt[d];
    int c = lane * 2;

    float2 acc0 = make_float2(0.f, 0.f), acc1 = make_float2(0.f, 0.f);
    float den0 = 0.f, den1 = 0.f;

    int sj_next = 0;
    if (lane < deg) sj_next = g_csrsrc[start + lane];

    for (int base = 0; base < deg; base += 32) {
        int m = min(32, deg - base);
        int sj = sj_next;
        int nb = base + 32;
        if (nb + lane < deg) sj_next = g_csrsrc[start + nb + lane];

        float w0 = 0.f, w1 = 0.f;
        if (lane < m) {
            float2 as = ((const float2*)g_asrc)[sj];
            w0 = __expf(lrelu(as.x + adp.x));
            w1 = __expf(lrelu(as.y + adp.y));
        }
        for (int k = 0; k < m; ++k) {
            int   s  = __shfl_sync(0xffffffffu, sj, k);
            float wa = __shfl_sync(0xffffffffu, w0, k);
            float wb = __shfl_sync(0xffffffffu, w1, k);
            const float* hr = h + (size_t)s * FF;
            float2 v0 = *(const float2*)(hr + c);
            float2 v1 = *(const float2*)(hr + CC + c);
            acc0.x += wa * v0.x; acc0.y += wa * v0.y;
            acc1.x += wb * v1.x; acc1.y += wb * v1.y;
            den0 += wa; den1 += wb;
        }
    }
    float i0 = 1.0f / (den0 + 1e-16f);
    float i1 = 1.0f / (den1 + 1e-16f);
    float2 b = ((const float2*)bias)[lane];
    float2 o = make_float2(0.5f * (acc0.x * i0 + acc1.x * i1) + b.x,
                           0.5f * (acc0.y * i0 + acc1.y * i1) + b.y);
    *(float2*)(out + (size_t)d * CC + c) = o;
}

// ---------------- final scorer ----------------
__global__ void score_pairs(const float* __restrict__ emb,
                            const int* __restrict__ uidx,
                            const int* __restrict__ iidx,
                            int nu, float* __restrict__ out, int B) {
    int warp = (blockIdx.x * blockDim.x + threadIdx.x) >> 5;
    int lane = threadIdx.x & 31;
    if (warp >= B) return;
    const float* gu = emb + (size_t)uidx[warp] * CC;
    const float* gi = emb + (size_t)(nu + iidx[warp]) * CC;
    float s = gu[lane] * gi[lane] + gu[lane + 32] * gi[lane + 32];
#pragma unroll
    for (int o = 16; o > 0; o >>= 1) s += __shfl_down_sync(0xffffffffu, s, o);
    if (lane == 0) out[warp] = s;
}

// ---------------- launch ----------------
extern "C" void kernel_launch(void* const* d_in, const int* in_sizes, int n_in,
                              void* d_out, int out_size) {
    const float* Gu  = (const float*)d_in[0];
    const float* Gi  = (const float*)d_in[1];
    const float* W0  = (const float*)d_in[2];
    const float* as0 = (const float*)d_in[3];
    const float* ad0 = (const float*)d_in[4];
    const float* b0  = (const float*)d_in[5];
    const float* W1  = (const float*)d_in[6];
    const float* as1 = (const float*)d_in[7];
    const float* ad1 = (const float*)d_in[8];
    const float* b1  = (const float*)d_in[9];
    const int*   ei  = (const int*)d_in[10];
    const int*   uix = (const int*)d_in[11];
    const int*   iix = (const int*)d_in[12];
    float* out = (float*)d_out;

    const int NU = in_sizes[0] / D0;
    const int NI = in_sizes[1] / D0;
    const int N  = NU + NI;
    const int E  = in_sizes[10] / 2;
    const int B  = in_sizes[11];
    const int* src = ei;
    const int* dst = ei + E;

    float *ph, *px1, *pout1;
    cudaGetSymbolAddress((void**)&ph,    g_h);
    cudaGetSymbolAddress((void**)&px1,   g_x1);
    cudaGetSymbolAddress((void**)&pout1, g_out1);

    const int TB = 256;
    int gemm_blocks  = (N + 15) / 16;
    int attn_grid    = (N * HH * 32 + TB - 1) / TB;
    int edge_grid    = (E + TB - 1) / TB;
    int node_grid    = (N + TB - 1) / TB;
    int warpnode_grid= (N * 32 + TB - 1) / TB;
    int scan_blocks  = (N + SCAN_BLK - 1) / SCAN_BLK;

    // ---------- CSR build (shared by both layers) ----------
    zero_cnt<<<node_grid, TB>>>(N);
    hist_dst<<<edge_grid, TB>>>(dst, E);
    scan1<<<scan_blocks, SCAN_BLK>>>(N);
    scan2<<<1, 256>>>(scan_blocks);
    scan3<<<scan_blocks, SCAN_BLK>>>(N);
    scatter_edges<<<edge_grid, TB>>>(src, dst, E);

    // ---------- layer 0 ----------
    gemm_rowpanel<D0><<<gemm_blocks, 256>>>(Gu, Gi, NU, W0, ph, N);
    attn_scores<<<attn_grid, TB>>>(ph, as0, ad0, N);
    agg_concat_csr<<<warpnode_grid, TB>>>(ph, b0, px1, N);

    // ---------- layer 1 ----------
    gemm_rowpanel<FF><<<gemm_blocks, 256>>>(px1, px1, N, W1, ph, N);
    attn_scores<<<attn_grid, TB>>>(ph, as1, ad1, N);
    agg_mean_csr<<<warpnode_grid, TB>>>(ph, b1, pout1, N);

    // ---------- scorer ----------
    score_pairs<<<(B * 32 + TB - 1) / TB, TB>>>(pout1, uix, iix, NU, out, B);
}